// round 1
// baseline (speedup 1.0000x reference)
#include <cuda_runtime.h>

// Per-step combined rotation constants (Rz(th1)*Ry(th0)), computed on device
// from theta by a tiny prep kernel. 32 steps x 2 float4 = 1 KB.
// c0 = (A=cc*cb,  sc,     B=cc*sb, D=sc*cb)
// c1 = (cc,       E=sc*sb, sb,     cb)
__device__ float4 g_consts[64];

__global__ void prep_consts_kernel(const float* __restrict__ theta) {
    int t = threadIdx.x;
    if (t < 32) {
        float th0 = theta[2 * t + 0];
        float th1 = theta[2 * t + 1];
        float cb = cosf(th0), sb = sinf(th0);   // Ry full angle (Bloch)
        float cc = cosf(th1), sc = sinf(th1);   // Rz full angle (Bloch)
        g_consts[2 * t + 0] = make_float4(cc * cb, sc, cc * sb, sc * cb);
        g_consts[2 * t + 1] = make_float4(cc, sc * sb, sb, cb);
    }
}

__global__ void __launch_bounds__(256) qsim_kernel(
    const float* __restrict__ x,
    const float* __restrict__ w,
    const float* __restrict__ b,
    float* __restrict__ out)
{
    __shared__ float4 sc_smem[64];
    int tid = threadIdx.x;
    if (tid < 64) sc_smem[tid] = g_consts[tid];
    __syncthreads();

    int i = blockIdx.x * blockDim.x + tid;

    // Load this element's full window up front: 8 x LDG.128, MLP=8.
    const float4* xp = reinterpret_cast<const float4*>(x + (size_t)i * 32);
    float4 xv[8];
#pragma unroll
    for (int k = 0; k < 8; k++) xv[k] = xp[k];
    const float* xs = reinterpret_cast<const float*>(xv);

    // Bloch vector of |0>
    float rx = 0.0f, ry = 0.0f, rz = 1.0f;

#pragma unroll
    for (int t = 0; t < 32; t++) {
        float xt = xs[t];
        float sx, cx;
        __sincosf(xt, &sx, &cx);           // 2x MUFU

        // Rx(xt): rotate (y,z)
        float y1 = cx * ry - sx * rz;
        float z1 = sx * ry + cx * rz;
        // x-component unchanged: x1 = rx

        float4 c0 = sc_smem[2 * t + 0];
        float4 c1 = sc_smem[2 * t + 1];
        // C = Rz(th1)*Ry(th0):
        // x' =  A*x  - sc*y1 + B*z1
        // y' =  D*x  + cc*y1 + E*z1
        // z' = -sb*x          + cb*z1
        float x2 = c0.x * rx - c0.y * y1 + c0.z * z1;
        float y2 = c0.w * rx + c1.x * y1 + c1.y * z1;
        float z2 = c1.w * z1 - c1.z * rx;

        rx = x2; ry = y2; rz = z2;
    }

    out[i] = rz * w[0] + b[0];
}

extern "C" void kernel_launch(void* const* d_in, const int* in_sizes, int n_in,
                              void* d_out, int out_size)
{
    const float* x     = (const float*)d_in[0];   // [B, 32]
    const float* theta = (const float*)d_in[1];   // [32, 2]
    const float* w     = (const float*)d_in[2];   // [1, 1]
    const float* b     = (const float*)d_in[3];   // [1]
    float* out = (float*)d_out;                   // [B]

    int B = in_sizes[0] / 32;

    prep_consts_kernel<<<1, 32>>>(theta);
    qsim_kernel<<<(B + 255) / 256, 256>>>(x, w, b, out);
}

// round 3
// speedup vs baseline: 1.0770x; 1.0770x over previous
#include <cuda_runtime.h>

typedef unsigned long long u64;

// ---------------------------------------------------------------------------
// Packed f32x2 helpers (Blackwell packed fp32 math)
// ---------------------------------------------------------------------------
__device__ __forceinline__ u64 pack2(float a, float b) {
    u64 r;
    asm("mov.b64 %0, {%1, %2};" : "=l"(r) : "f"(a), "f"(b));
    return r;
}
__device__ __forceinline__ void unpack2(u64 v, float& a, float& b) {
    asm("mov.b64 {%0, %1}, %2;" : "=f"(a), "=f"(b) : "l"(v));
}
__device__ __forceinline__ u64 fma2(u64 a, u64 b, u64 c) {
    u64 r;
    asm("fma.rn.f32x2 %0, %1, %2, %3;" : "=l"(r) : "l"(a), "l"(b), "l"(c));
    return r;
}
__device__ __forceinline__ u64 mul2(u64 a, u64 b) {
    u64 r;
    asm("mul.rn.f32x2 %0, %1, %2;" : "=l"(r) : "l"(a), "l"(b));
    return r;
}

// ---------------------------------------------------------------------------
// Per-step combined rotation constants (Bloch-sphere form of Rz(th1)*Ry(th0)),
// pre-duplicated into both lanes of a f32x2 so the main loop needs no packing.
// Layout per step t (8 u64): A=cc*cb, nSC=-sc, B=cc*sb, D=sc*cb,
//                            CC=cc, E=sc*sb, nSB=-sb, CB=cb
// ---------------------------------------------------------------------------
__device__   u64 g_consts_dev[32 * 8];   // staging (written by prep kernel)
__constant__ u64 c_consts[32 * 8];       // read by main kernel via const bank

__global__ void prep_consts_kernel(const float* __restrict__ theta) {
    int t = threadIdx.x;
    if (t < 32) {
        float th0 = theta[2 * t + 0];
        float th1 = theta[2 * t + 1];
        float sb = sinf(th0), cb = cosf(th0);  // Ry full angle (Bloch sphere)
        float sc = sinf(th1), cc = cosf(th1);  // Rz full angle (Bloch sphere)
        float v[8] = { cc * cb, -sc, cc * sb, sc * cb,
                       cc, sc * sb, -sb, cb };
#pragma unroll
        for (int k = 0; k < 8; k++) {
            u64 p;
            asm("mov.b64 %0, {%1, %1};" : "=l"(p) : "f"(v[k]));
            g_consts_dev[t * 8 + k] = p;
        }
    }
}

// ---------------------------------------------------------------------------
// Main kernel: each thread evolves TWO windows (ILP=2) through 32 steps of
//   r <- Rz(th1) * Ry(th0) * Rx(x_t) * r        (r = Bloch vector, r0=(0,0,1))
// using packed f32x2 arithmetic. Output = r.z * w + b.
// ---------------------------------------------------------------------------
__global__ void __launch_bounds__(256) qsim_kernel(
    const float* __restrict__ x,
    const float* __restrict__ w,
    const float* __restrict__ b,
    float* __restrict__ out)
{
    int tid = threadIdx.x;
    size_t e0 = (size_t)blockIdx.x * 512 + tid;       // element for lane .x
    size_t e1 = e0 + 256;                             // element for lane .y

    const float4* xp0 = reinterpret_cast<const float4*>(x + e0 * 32);
    const float4* xp1 = reinterpret_cast<const float4*>(x + e1 * 32);

    // Bloch vector of |0> for both elements
    u64 rx = pack2(0.0f, 0.0f);
    u64 ry = rx;
    u64 rz = pack2(1.0f, 1.0f);

#pragma unroll
    for (int c = 0; c < 8; c++) {
        float4 a0 = xp0[c];                           // LDG.128 (elem 0)
        float4 a1 = xp1[c];                           // LDG.128 (elem 1)
        float xa0[4] = { a0.x, a0.y, a0.z, a0.w };
        float xa1[4] = { a1.x, a1.y, a1.z, a1.w };

#pragma unroll
        for (int j = 0; j < 4; j++) {
            int t = c * 4 + j;

            float s0, c0, s1, c1;
            __sincosf(xa0[j], &s0, &c0);              // 2x MUFU
            __sincosf(xa1[j], &s1, &c1);              // 2x MUFU

            u64 sx  = pack2(s0, s1);
            u64 cx  = pack2(c0, c1);
            u64 nsx = pack2(-s0, -s1);

            const u64* cs = &c_consts[t * 8];         // const-bank, uniform
            u64 A   = cs[0];
            u64 nSC = cs[1];
            u64 Bc  = cs[2];
            u64 D   = cs[3];
            u64 CC  = cs[4];
            u64 E   = cs[5];
            u64 nSB = cs[6];
            u64 CB  = cs[7];

            // Rx(x_t): rotate (y,z); x unchanged
            u64 y1 = fma2(cx, ry, mul2(nsx, rz));     // cx*ry - sx*rz
            u64 z1 = fma2(sx, ry, mul2(cx, rz));      // sx*ry + cx*rz

            // C = Rz(th1)*Ry(th0) applied to (rx, y1, z1):
            u64 x2 = fma2(Bc, z1, fma2(nSC, y1, mul2(A, rx)));
            u64 y2 = fma2(E,  z1, fma2(CC,  y1, mul2(D, rx)));
            u64 z2 = fma2(nSB, rx, mul2(CB, z1));

            rx = x2; ry = y2; rz = z2;
        }
    }

    float W  = w[0];
    float Bb = b[0];
    float z_0, z_1;
    unpack2(rz, z_0, z_1);
    out[e0] = fmaf(z_0, W, Bb);
    out[e1] = fmaf(z_1, W, Bb);
}

extern "C" void kernel_launch(void* const* d_in, const int* in_sizes, int n_in,
                              void* d_out, int out_size)
{
    const float* x     = (const float*)d_in[0];   // [B, 32]
    const float* theta = (const float*)d_in[1];   // [32, 2]
    const float* w     = (const float*)d_in[2];   // [1, 1]
    const float* b     = (const float*)d_in[3];   // [1]
    float* out = (float*)d_out;                   // [B]

    int B = in_sizes[0] / 32;

    prep_consts_kernel<<<1, 32>>>(theta);

    // Stage -> constant bank (device-to-device, graph-capturable memcpy node)
    void* staging_ptr = nullptr;
    cudaGetSymbolAddress(&staging_ptr, g_consts_dev);
    cudaMemcpyToSymbolAsync(c_consts, staging_ptr, sizeof(u64) * 32 * 8, 0,
                            cudaMemcpyDeviceToDevice, 0);

    // 512 elements per block (ILP=2 per thread)
    qsim_kernel<<<B / 512, 256>>>(x, w, b, out);
}

// round 7
// speedup vs baseline: 1.5208x; 1.4121x over previous
#include <cuda_runtime.h>

typedef unsigned long long u64;

// ---------------------------------------------------------------------------
// Packed f32x2 helpers (Blackwell packed fp32 math)
// ---------------------------------------------------------------------------
__device__ __forceinline__ u64 pack2(float a, float b) {
    u64 r;
    asm("mov.b64 %0, {%1, %2};" : "=l"(r) : "f"(a), "f"(b));
    return r;
}
__device__ __forceinline__ void unpack2(u64 v, float& a, float& b) {
    asm("mov.b64 {%0, %1}, %2;" : "=f"(a), "=f"(b) : "l"(v));
}
__device__ __forceinline__ u64 fma2(u64 a, u64 b, u64 c) {
    u64 r;
    asm("fma.rn.f32x2 %0, %1, %2, %3;" : "=l"(r) : "l"(a), "l"(b), "l"(c));
    return r;
}
__device__ __forceinline__ u64 mul2(u64 a, u64 b) {
    u64 r;
    asm("mul.rn.f32x2 %0, %1, %2;" : "=l"(r) : "l"(a), "l"(b));
    return r;
}

// ---------------------------------------------------------------------------
// Per-step combined rotation constants (Bloch form of Rz(th1)*Ry(th0)),
// duplicated into both f32x2 lanes. Layout per step t (8 u64):
//   A=cc*cb, nSC=-sc, B=cc*sb, D=sc*cb, CC=cc, E=sc*sb, nSB=-sb, CB=cb
// ---------------------------------------------------------------------------
__device__   u64 g_consts_dev[32 * 8];
__constant__ u64 c_consts[32 * 8];

__global__ void prep_consts_kernel(const float* __restrict__ theta) {
    int t = threadIdx.x;
    if (t < 32) {
        float th0 = theta[2 * t + 0];
        float th1 = theta[2 * t + 1];
        float sb = sinf(th0), cb = cosf(th0);  // Ry full angle (Bloch sphere)
        float sc = sinf(th1), cc = cosf(th1);  // Rz full angle (Bloch sphere)
        float v[8] = { cc * cb, -sc, cc * sb, sc * cb,
                       cc, sc * sb, -sb, cb };
#pragma unroll
        for (int k = 0; k < 8; k++) {
            u64 p;
            asm("mov.b64 %0, {%1, %1};" : "=l"(p) : "f"(v[k]));
            g_consts_dev[t * 8 + k] = p;
        }
    }
}

// ---------------------------------------------------------------------------
// Main kernel. Block of 256 threads owns 512 contiguous elements.
// Phase 1: coalesced LDG.128 of the block's contiguous 64KB x-region into
//          smem with XOR-quad swizzle (slot = (c+e)&7) so both the coalesced
//          store and the strided per-element read are LDS.128 conflict-free.
// Phase 2: each thread evolves TWO elements (packed f32x2 lanes) through
//          r <- Rz(th1)*Ry(th0)*Rx(x_t)*r on the Bloch sphere; out = r.z*w+b.
// ---------------------------------------------------------------------------
__global__ void __launch_bounds__(256) qsim_kernel(
    const float4* __restrict__ xg,
    const float* __restrict__ w,
    const float* __restrict__ b,
    float* __restrict__ out)
{
    extern __shared__ float4 s_x[];   // 512 elements * 8 float4 = 64KB

    int tid = threadIdx.x;
    size_t blockElem = (size_t)blockIdx.x * 512;
    const float4* gbase = xg + blockElem * 8;

    // Coalesced streaming load -> swizzled smem store
#pragma unroll
    for (int k = 0; k < 16; k++) {
        int idx = tid + k * 256;            // linear float4 index in block tile
        float4 v = __ldcs(gbase + idx);     // lanes consecutive: nL=4 per warp
        int e = idx >> 3;                   // local element
        int c = idx & 7;                    // chunk within window
        s_x[(e << 3) + ((c + e) & 7)] = v;  // XOR-quad swizzle
    }
    __syncthreads();

    int e0 = tid;          // lane .x element (local)
    int e1 = tid + 256;    // lane .y element (local)

    // Bloch vector of |0> for both elements
    u64 rx = pack2(0.0f, 0.0f);
    u64 ry = rx;
    u64 rz = pack2(1.0f, 1.0f);

#pragma unroll
    for (int c = 0; c < 8; c++) {
        float4 a0 = s_x[(e0 << 3) + ((c + e0) & 7)];   // LDS.128, conflict-free
        float4 a1 = s_x[(e1 << 3) + ((c + e1) & 7)];
        float xa0[4] = { a0.x, a0.y, a0.z, a0.w };
        float xa1[4] = { a1.x, a1.y, a1.z, a1.w };

#pragma unroll
        for (int j = 0; j < 4; j++) {
            int t = c * 4 + j;

            float s0, c0, s1, c1;
            __sincosf(xa0[j], &s0, &c0);               // 2x MUFU
            __sincosf(xa1[j], &s1, &c1);               // 2x MUFU

            u64 sx  = pack2(s0, s1);
            u64 cx  = pack2(c0, c1);
            u64 nsx = pack2(-s0, -s1);

            const u64* cs = &c_consts[t * 8];          // const bank (LDC), uniform
            u64 A   = cs[0];
            u64 nSC = cs[1];
            u64 Bc  = cs[2];
            u64 D   = cs[3];
            u64 CC  = cs[4];
            u64 E   = cs[5];
            u64 nSB = cs[6];
            u64 CB  = cs[7];

            // Rx(x_t): rotate (y,z); x unchanged
            u64 y1 = fma2(cx, ry, mul2(nsx, rz));      // cx*ry - sx*rz
            u64 z1 = fma2(sx, ry, mul2(cx, rz));       // sx*ry + cx*rz

            // Rz(th1)*Ry(th0) applied to (rx, y1, z1):
            u64 x2 = fma2(Bc, z1, fma2(nSC, y1, mul2(A, rx)));
            u64 y2 = fma2(E,  z1, fma2(CC,  y1, mul2(D, rx)));
            u64 z2 = fma2(nSB, rx, mul2(CB, z1));

            rx = x2; ry = y2; rz = z2;
        }
    }

    float W  = w[0];
    float Bb = b[0];
    float z_0, z_1;
    unpack2(rz, z_0, z_1);
    out[blockElem + e0] = fmaf(z_0, W, Bb);            // coalesced stores
    out[blockElem + e1] = fmaf(z_1, W, Bb);
}

extern "C" void kernel_launch(void* const* d_in, const int* in_sizes, int n_in,
                              void* d_out, int out_size)
{
    const float* x     = (const float*)d_in[0];   // [B, 32]
    const float* theta = (const float*)d_in[1];   // [32, 2]
    const float* w     = (const float*)d_in[2];   // [1, 1]
    const float* b     = (const float*)d_in[3];   // [1]
    float* out = (float*)d_out;                   // [B]

    int B = in_sizes[0] / 32;

    prep_consts_kernel<<<1, 32>>>(theta);

    // Stage -> constant bank (device-to-device memcpy node, graph-capturable)
    void* staging_ptr = nullptr;
    cudaGetSymbolAddress(&staging_ptr, g_consts_dev);
    cudaMemcpyToSymbolAsync(c_consts, staging_ptr, sizeof(u64) * 32 * 8, 0,
                            cudaMemcpyDeviceToDevice, 0);

    const int SMEM = 512 * 8 * sizeof(float4);    // 64KB dynamic smem
    cudaFuncSetAttribute(qsim_kernel, cudaFuncAttributeMaxDynamicSharedMemorySize, SMEM);

    qsim_kernel<<<B / 512, 256, SMEM>>>((const float4*)x, w, b, out);
}